// round 11
// baseline (speedup 1.0000x reference)
#include <cstdint>
#include <cuda_runtime.h>
#include <cuda_bf16.h>

#define NG   2048
#define NSEG 8
#define SEGSZ (NG / NSEG)   // 256
#define NPIX (128 * 128)
#define NEAR_Z 0.3f
#define EPS_C 0.0001f

#define RB 64          // rank blocks
#define RT 256         // threads per rank block
#define TPG 8          // threads per gaussian
#define NF4 (NG / 4)   // 512 float4 keys

// ---------------- device scratch (no allocations allowed) ----------------
__device__ float4 d_bbox[NG];          // sorted: u, v, rx, ry
__device__ float4 d_conic[NG];         // sorted: A, B, C, opa_eff
__device__ float4 d_color[NG];         // sorted: r, g, b, depth

__device__ __forceinline__ float sigmoidf(float x) {
    return 1.0f / (1.0f + __expf(-x));
}

// ---------------- 1. keys + rank + prep + scatter (fused) ----------------
__global__ void __launch_bounds__(RT) prep_rank_kernel(
        const float* __restrict__ pos,
        const float* __restrict__ rgb,
        const float* __restrict__ opa,
        const float* __restrict__ quat,
        const float* __restrict__ scale,
        const float* __restrict__ rot,
        const float* __restrict__ tran) {
    __shared__ __align__(16) float s_r[NG];   // 8 KB
    int tid = threadIdx.x;

    float R00 = rot[0], R01 = rot[1], R02 = rot[2];
    float R10 = rot[3], R11 = rot[4], R12 = rot[5];
    float R20 = rot[6], R21 = rot[7], R22 = rot[8];
    float t0 = tran[0], t1 = tran[1], t2 = tran[2];

    // ---- phase A: all 2048 depth keys (each block, redundantly) ----
#pragma unroll
    for (int j = tid; j < NG; j += RT) {
        float p0 = pos[3 * j + 0], p1 = pos[3 * j + 1], p2 = pos[3 * j + 2];
        float x = R00 * p0 + R01 * p1 + R02 * p2 + t0;
        float y = R10 * p0 + R11 * p1 + R12 * p2 + t1;
        float z = R20 * p0 + R21 * p1 + R22 * p2 + t2;
        s_r[j] = sqrtf(x * x + y * y + z * z);
    }
    __syncthreads();

    // ---- phase B: stable rank, interleaved conflict-free scan ----
    int g = (blockIdx.x * RT + tid) >> 3;    // 0..2047
    int q = tid & 7;                         // sub-rank
    float rg = s_r[g];

    int cnt = 0;
    const float4* s4 = reinterpret_cast<const float4*>(s_r);
#pragma unroll 8
    for (int i = 0; i < NF4 / TPG; i++) {
        int f = i * TPG + q;                 // lanes 0..7 hit consecutive 16B
        int j = f * 4;
        float4 v = s4[f];
        cnt += (v.x < rg) || (v.x == rg && (j + 0) < g);
        cnt += (v.y < rg) || (v.y == rg && (j + 1) < g);
        cnt += (v.z < rg) || (v.z == rg && (j + 2) < g);
        cnt += (v.w < rg) || (v.w == rg && (j + 3) < g);
    }
    cnt += __shfl_xor_sync(0xffffffffu, cnt, 1);
    cnt += __shfl_xor_sync(0xffffffffu, cnt, 2);
    cnt += __shfl_xor_sync(0xffffffffu, cnt, 4);
    int rank = cnt;

    if (q != 0) return;

    // ---- phase C: leader does full projection + scatter ----
    float p0 = pos[3 * g + 0], p1 = pos[3 * g + 1], p2 = pos[3 * g + 2];
    float x = R00 * p0 + R01 * p1 + R02 * p2 + t0;
    float y = R10 * p0 + R11 * p1 + R12 * p2 + t1;
    float z = R20 * p0 + R21 * p1 + R22 * p2 + t2;

    float r = rg;
    float iz = 1.0f / z;
    float u = x * iz, v = y * iz;

    float J00 = iz, J02 = -x * iz * iz;
    float J11 = iz, J12 = -y * iz * iz;

    float W00 = J00 * R00 + J02 * R20;
    float W01 = J00 * R01 + J02 * R21;
    float W02 = J00 * R02 + J02 * R22;
    float W10 = J11 * R10 + J12 * R20;
    float W11 = J11 * R11 + J12 * R21;
    float W12 = J11 * R12 + J12 * R22;

    float qw = quat[4 * g + 0], qx = quat[4 * g + 1];
    float qy = quat[4 * g + 2], qz = quat[4 * g + 3];
    float qn = rsqrtf(qw * qw + qx * qx + qy * qy + qz * qz);
    qw *= qn; qx *= qn; qy *= qn; qz *= qn;
    float m00 = 1.0f - 2.0f * (qy * qy + qz * qz);
    float m01 = 2.0f * (qx * qy - qw * qz);
    float m02 = 2.0f * (qx * qz + qw * qy);
    float m10 = 2.0f * (qx * qy + qw * qz);
    float m11 = 1.0f - 2.0f * (qx * qx + qz * qz);
    float m12 = 2.0f * (qy * qz - qw * qx);
    float m20 = 2.0f * (qx * qz - qw * qy);
    float m21 = 2.0f * (qy * qz + qw * qx);
    float m22 = 1.0f - 2.0f * (qx * qx + qy * qy);

    float s0 = fabsf(scale[3 * g + 0]) + 1e-4f;
    float s1 = fabsf(scale[3 * g + 1]) + 1e-4f;
    float s2 = fabsf(scale[3 * g + 2]) + 1e-4f;

    float M00 = m00 * s0, M01 = m01 * s1, M02 = m02 * s2;
    float M10 = m10 * s0, M11 = m11 * s1, M12 = m12 * s2;
    float M20 = m20 * s0, M21 = m21 * s1, M22 = m22 * s2;

    float c00 = M00 * M00 + M01 * M01 + M02 * M02;
    float c01 = M00 * M10 + M01 * M11 + M02 * M12;
    float c02 = M00 * M20 + M01 * M21 + M02 * M22;
    float c11 = M10 * M10 + M11 * M11 + M12 * M12;
    float c12 = M10 * M20 + M11 * M21 + M12 * M22;
    float c22 = M20 * M20 + M21 * M21 + M22 * M22;

    float u0 = c00 * W00 + c01 * W01 + c02 * W02;
    float u1 = c01 * W00 + c11 * W01 + c12 * W02;
    float u2 = c02 * W00 + c12 * W01 + c22 * W02;
    float a = W00 * u0 + W01 * u1 + W02 * u2 + EPS_C;
    float b = W10 * u0 + W11 * u1 + W12 * u2;
    float w0 = c00 * W10 + c01 * W11 + c02 * W12;
    float w1 = c01 * W10 + c11 * W11 + c12 * W12;
    float w2 = c02 * W10 + c12 * W11 + c22 * W12;
    float c = W10 * w0 + W11 * w1 + W12 * w2 + EPS_C;

    float det = a * c - b * b;
    float idet = 1.0f / det;
    float A = -0.5f * c * idet;
    float B = b * idet;            // == -ib
    float C = -0.5f * a * idet;

    float op = sigmoidf(opa[g]);
    float rx, ry;
    if (z > NEAR_Z) {
        rx = 6.0f * sqrtf(a);      // power <= -18 outside
        ry = 6.0f * sqrtf(c);
    } else {
        op = 0.0f; rx = -1.0f; ry = -1.0f;
        A = 0.0f; B = 0.0f; C = 0.0f;
    }

    float cr = sigmoidf(rgb[3 * g + 0]);
    float cg = sigmoidf(rgb[3 * g + 1]);
    float cb = sigmoidf(rgb[3 * g + 2]);

    d_bbox[rank]  = make_float4(u, v, rx, ry);
    d_conic[rank] = make_float4(A, B, C, op);
    d_color[rank] = make_float4(cr, cg, cb, r);
}

// ---------------- 2. fused render + cluster combine ----------------
// Cluster of 8 CTAs = 8 depth segments of ONE 16x16 tile. 256 threads =
// 8 warps, each an 8x4 pixel window. Hits are processed TWO per loop
// iteration (warp-uniform predicated second slot) to halve the per-hit
// branch/ffs overhead and double ILP across the exp/math chains.
__device__ __forceinline__ uint32_t smem_u32(const void* p) {
    uint32_t a;
    asm("{ .reg .u64 t; cvta.to.shared.u64 t, %1; cvt.u32.u64 %0, t; }"
        : "=r"(a) : "l"(p));
    return a;
}

__global__ void __launch_bounds__(256) __cluster_dims__(8, 1, 1)
render_kernel(float* __restrict__ out) {
    __shared__ float4 sb[SEGSZ];
    __shared__ float4 sc[SEGSZ];
    __shared__ float4 sl[SEGSZ];
    __shared__ float4 s_part[256];   // this segment's partials for the tile

    int tid  = threadIdx.x;
    int bx   = blockIdx.x;      // 0..511
    int tile = bx >> 3;         // 64 tiles
    int seg  = bx & 7;          // == cluster rank
    int gbase = seg * SEGSZ;

    sb[tid] = d_bbox[gbase + tid];
    sc[tid] = d_conic[gbase + tid];
    sl[tid] = d_color[gbase + tid];
    __syncthreads();

    int w = tid >> 5, lane = tid & 31;
    int tx = tile & 7, ty = tile >> 3;
    int lxb = (w & 1) << 3;
    int lyb = (w >> 1) << 2;
    int lx = lxb + (lane & 7);
    int ly = lyb + (lane >> 3);
    int ix = tx * 16 + lx;
    int iy = ty * 16 + ly;

    const float inv = 1.0f / 128.0f;
    float pxf = (ix - 63.5f) * inv;
    float pyf = (iy - 63.5f) * inv;
    float wx0 = (tx * 16 + lxb - 63.5f) * inv, wx1 = wx0 + 7.0f * inv;
    float wy0 = (ty * 16 + lyb - 63.5f) * inv, wy1 = wy0 + 3.0f * inv;

    float T = 1.0f, ar = 0.0f, ag = 0.0f, ab = 0.0f;

    for (int base = 0; base < SEGSZ; base += 32) {
        float4 bb = sb[base + lane];
        bool hit = (bb.x - bb.z <= wx1) && (bb.x + bb.z >= wx0) &&
                   (bb.y - bb.w <= wy1) && (bb.y + bb.w >= wy0);
        unsigned m = __ballot_sync(0xffffffffu, hit);
        while (m) {
            int j0 = __ffs(m) - 1;
            m &= m - 1;
            int j1 = j0;
            float en1 = 0.0f;
            if (m) {                      // warp-uniform; compiles branch-free
                j1 = __ffs(m) - 1;
                m &= m - 1;
                en1 = 1.0f;
            }
            float4 qv0 = sb[base + j0];
            float4 cn0 = sc[base + j0];
            float4 cl0 = sl[base + j0];
            float4 qv1 = sb[base + j1];
            float4 cn1 = sc[base + j1];
            float4 cl1 = sl[base + j1];

            float dx0 = pxf - qv0.x, dy0 = pyf - qv0.y;
            float dx1 = pxf - qv1.x, dy1 = pyf - qv1.y;
            float pw0 = fmaf(cn0.x * dx0, dx0, fmaf(cn0.y * dx0, dy0, cn0.z * dy0 * dy0));
            float pw1 = fmaf(cn1.x * dx1, dx1, fmaf(cn1.y * dx1, dy1, cn1.z * dy1 * dy1));
            float a0 = fminf(cn0.w * __expf(pw0), 0.99f);
            float a1 = fminf(cn1.w * __expf(pw1), 0.99f) * en1;

            float wt0 = T * a0;
            ar = fmaf(wt0, cl0.x, ar);
            ag = fmaf(wt0, cl0.y, ag);
            ab = fmaf(wt0, cl0.z, ab);
            T -= wt0;
            float wt1 = T * a1;
            ar = fmaf(wt1, cl1.x, ar);
            ag = fmaf(wt1, cl1.y, ag);
            ab = fmaf(wt1, cl1.z, ab);
            T -= wt1;
        }
        if (__all_sync(0xffffffffu, T < 1e-7f)) break;
    }

    s_part[ly * 16 + lx] = make_float4(ar, ag, ab, T);

    // ---- cluster barrier: all segments' partials visible ----
    asm volatile("barrier.cluster.arrive.aligned;" ::: "memory");
    asm volatile("barrier.cluster.wait.aligned;" ::: "memory");

    // ---- combine: 8 lanes per pixel, one peer segment each ----
    int tseg = tid & 7;                 // which peer segment this lane reads
    int pl   = seg * 32 + (tid >> 3);   // pixel handled by this CTA's slice

    uint32_t laddr = smem_u32(&s_part[pl]);
    uint32_t paddr;
    asm("mapa.shared::cluster.u32 %0, %1, %2;" : "=r"(paddr)
        : "r"(laddr), "r"(tseg));
    float cr_, cg_, cb_, ct_;
    asm volatile("ld.shared::cluster.v4.f32 {%0,%1,%2,%3}, [%4];"
                 : "=f"(cr_), "=f"(cg_), "=f"(cb_), "=f"(ct_) : "r"(paddr));

    // exclusive product-scan of T over the 8 seg-lanes (front-to-back)
    float tp = ct_;
#pragma unroll
    for (int d = 1; d < 8; d <<= 1) {
        float v = __shfl_up_sync(0xffffffffu, tp, d, 8);
        if ((tid & 7) >= d) tp *= v;
    }
    float texcl = __shfl_up_sync(0xffffffffu, tp, 1, 8);
    if (tseg == 0) texcl = 1.0f;

    float orr = texcl * cr_, og = texcl * cg_, ob = texcl * cb_;
#pragma unroll
    for (int d = 1; d < 8; d <<= 1) {
        orr += __shfl_xor_sync(0xffffffffu, orr, d, 8);
        og  += __shfl_xor_sync(0xffffffffu, og,  d, 8);
        ob  += __shfl_xor_sync(0xffffffffu, ob,  d, 8);
    }

    if (tseg == 0) {
        int gx = tx * 16 + (pl & 15);
        int gy = ty * 16 + (pl >> 4);
        int o = 3 * (gy * 128 + gx);
        out[o + 0] = orr;
        out[o + 1] = og;
        out[o + 2] = ob;
    }

    // don't exit while peers may still be reading our s_part
    asm volatile("barrier.cluster.arrive.aligned;" ::: "memory");
    asm volatile("barrier.cluster.wait.aligned;" ::: "memory");
}

// ---------------- launch ----------------
extern "C" void kernel_launch(void* const* d_in, const int* in_sizes, int n_in,
                              void* d_out, int out_size) {
    const float* pos   = (const float*)d_in[0];
    const float* rgb   = (const float*)d_in[1];
    const float* opa   = (const float*)d_in[2];
    const float* quat  = (const float*)d_in[3];
    const float* scale = (const float*)d_in[4];
    const float* rot   = (const float*)d_in[5];
    const float* tran  = (const float*)d_in[6];
    float* out = (float*)d_out;

    prep_rank_kernel<<<RB, RT>>>(pos, rgb, opa, quat, scale, rot, tran);
    render_kernel<<<512, 256>>>(out);
}